// round 10
// baseline (speedup 1.0000x reference)
#include <cuda_runtime.h>
#include <cuda_bf16.h>
#include <cstdint>
#include <math_constants.h>

#define EPS 1e-5f
#define HB 64
#define BATCH 128
#define CIN 2048
#define CMID 512
#define HW 196
#define HWP 256
#define KXT 224     // xxt effective K (>=196, /32)
#define K33 4608
#define NFLAT 25088   // 128*196 = 196 tiles of 128 exactly

// ---------------- scratch (static device globals; zero-init at load) --------
__device__ __nv_bfloat16 g_fT_h[(size_t)NFLAT * CIN];
__device__ __nv_bfloat16 g_fT_l[(size_t)NFLAT * CIN];
__device__ __nv_bfloat16 g_x_h [(size_t)BATCH * CMID * HWP];  // pad cols stay 0
__device__ __nv_bfloat16 g_x_l [(size_t)BATCH * CMID * HWP];
__device__ __nv_bfloat16 g_xT_h[(size_t)BATCH * HW * CMID];
__device__ float         g_att [(size_t)BATCH * CMID * CMID];
__device__ __nv_bfloat16 g_att_h[(size_t)BATCH * CMID * CMID];
__device__ __nv_bfloat16 g_att_l[(size_t)BATCH * CMID * CMID];
__device__ __nv_bfloat16 g_y_ch[(size_t)BATCH * CMID * HWP];  // y, [b][c][hw]
__device__ __nv_bfloat16 g_yT_h[(size_t)BATCH * HW * CMID];
__device__ __nv_bfloat16 g_w1_h[(size_t)CMID * CIN];
__device__ __nv_bfloat16 g_w1_l[(size_t)CMID * CIN];
__device__ __nv_bfloat16 g_w3_h[(size_t)CMID * K33];   // reordered k = rs*512 + c
__device__ __nv_bfloat16 g_w3_l[(size_t)CMID * K33];
__device__ float g_zsum[BATCH * CMID];
__device__ float g_h[BATCH * 200];
__device__ float g_scale1[CMID], g_shift1[CMID], g_scale3[CMID], g_shift3[CMID];

// ---------------- ptx helpers (all non-'a' gated: sm_80-level) --------------
__device__ __forceinline__ uint32_t smem_u32(const void* p) {
    uint32_t a;
    asm("{ .reg .u64 t; cvta.to.shared.u64 t, %1; cvt.u32.u64 %0, t; }"
        : "=r"(a) : "l"(p));
    return a;
}
__device__ __forceinline__ void cp16(uint32_t dst, const void* src) {
    asm volatile("cp.async.ca.shared.global [%0], [%1], 16;"
                 :: "r"(dst), "l"(src));
}
__device__ __forceinline__ void cp16z(uint32_t dst, const void* src, int ok) {
    int sz = ok ? 16 : 0;
    asm volatile("cp.async.ca.shared.global [%0], [%1], 16, %2;"
                 :: "r"(dst), "l"(src), "r"(sz));
}
__device__ __forceinline__ void cp_commit() {
    asm volatile("cp.async.commit_group;" ::: "memory");
}
template<int N> __device__ __forceinline__ void cp_wait() {
    asm volatile("cp.async.wait_group %0;" :: "n"(N) : "memory");
}
__device__ __forceinline__ void ldm4(uint32_t* r, uint32_t addr) {
    asm volatile("ldmatrix.sync.aligned.m8n8.x4.shared.b16 {%0,%1,%2,%3}, [%4];"
                 : "=r"(r[0]), "=r"(r[1]), "=r"(r[2]), "=r"(r[3]) : "r"(addr));
}
__device__ __forceinline__ void ldm2(uint32_t* r, uint32_t addr) {
    asm volatile("ldmatrix.sync.aligned.m8n8.x2.shared.b16 {%0,%1}, [%2];"
                 : "=r"(r[0]), "=r"(r[1]) : "r"(addr));
}
__device__ __forceinline__ void mma16816(float* c, const uint32_t* a,
                                         const uint32_t* b) {
    asm volatile(
        "mma.sync.aligned.m16n8k16.row.col.f32.bf16.bf16.f32 "
        "{%0,%1,%2,%3}, {%4,%5,%6,%7}, {%8,%9}, {%0,%1,%2,%3};"
        : "+f"(c[0]), "+f"(c[1]), "+f"(c[2]), "+f"(c[3])
        : "r"(a[0]), "r"(a[1]), "r"(a[2]), "r"(a[3]), "r"(b[0]), "r"(b[1]));
}
__device__ __forceinline__ void split_bf16(float v, __nv_bfloat16& hi,
                                           __nv_bfloat16& lo) {
    hi = __float2bfloat16(v);
    lo = __float2bfloat16(v - __bfloat162float(hi));
}

// ---------------- SMEM geometry ---------------------------------------------
#define TROW 80
#define TILE_B (128 * TROW)          // 10240 B
#define STAGE_B (4 * TILE_B)         // Ah, Al, Bh, Bl (reduce/xxt)
#define STAGE3_B (3 * TILE_B)        // Ah, Al, Bh     (ygemm/conv)
#define DYN_SMEM (2 * STAGE_B)       // 81920 B
#define DYN3_SMEM (3 * STAGE3_B)     // 92160 B (conv, 3-stage)
#define DYN3B_SMEM (2 * STAGE3_B)    // 61440 B (ygemm, 2-stage)

// contiguous 128x32 tile load via cp.async: 512 16B chunks / 256 threads
__device__ __forceinline__ void cpa_tile(uint32_t sdst, const __nv_bfloat16* g,
                                         size_t stride, int k0, int tid) {
    #pragma unroll
    for (int it = 0; it < 2; it++) {
        int ch = it * 256 + tid;
        int row = ch >> 2, seg = ch & 3;
        cp16(sdst + row * TROW + seg * 16,
             g + (size_t)row * stride + k0 + seg * 8);
    }
}
__device__ __forceinline__ void cpa_tile_clamp(uint32_t sdst,
                                               const __nv_bfloat16* g,
                                               size_t stride, int row0,
                                               int maxrow, int k0, int tid) {
    #pragma unroll
    for (int it = 0; it < 2; it++) {
        int ch = it * 256 + tid;
        int row = ch >> 2, seg = ch & 3;
        int rg = row0 + row; if (rg > maxrow) rg = maxrow;
        cp16(sdst + row * TROW + seg * 16,
             g + (size_t)rg * stride + k0 + seg * 8);
    }
}

// one k16 slab: 4 m-atoms x 4 n-atoms of m16n8k16
__device__ __forceinline__ void mma_k16(uint32_t aBase, uint32_t bBase, int kk,
                                        int lane, float c[4][4][4]) {
    uint32_t a[4][4], b[4][2];
    int arow = lane & 15, asel = lane >> 4;
    #pragma unroll
    for (int am = 0; am < 4; am++)
        ldm4(a[am], aBase + (am * 16 + arow) * TROW + (kk + asel * 8) * 2);
    int brow = lane & 7, bsel = (lane >> 3) & 1;
    #pragma unroll
    for (int bn = 0; bn < 4; bn++)
        ldm2(b[bn], bBase + (bn * 8 + brow) * TROW + (kk + bsel * 8) * 2);
    #pragma unroll
    for (int am = 0; am < 4; am++)
        #pragma unroll
        for (int bn = 0; bn < 4; bn++)
            mma16816(c[am][bn], a[am], b[bn]);
}

// 2-A variant: (Ahi + Alo) x B, B fragments loaded once
__device__ __forceinline__ void mma_k16_2A(uint32_t aH, uint32_t aL,
                                           uint32_t bBase, int kk, int lane,
                                           float c[4][4][4]) {
    uint32_t a[4][4], b[4][2];
    int arow = lane & 15, asel = lane >> 4;
    int brow = lane & 7, bsel = (lane >> 3) & 1;
    #pragma unroll
    for (int bn = 0; bn < 4; bn++)
        ldm2(b[bn], bBase + (bn * 8 + brow) * TROW + (kk + bsel * 8) * 2);
    #pragma unroll
    for (int am = 0; am < 4; am++)
        ldm4(a[am], aH + (am * 16 + arow) * TROW + (kk + asel * 8) * 2);
    #pragma unroll
    for (int am = 0; am < 4; am++)
        #pragma unroll
        for (int bn = 0; bn < 4; bn++)
            mma16816(c[am][bn], a[am], b[bn]);
    #pragma unroll
    for (int am = 0; am < 4; am++)
        ldm4(a[am], aL + (am * 16 + arow) * TROW + (kk + asel * 8) * 2);
    #pragma unroll
    for (int am = 0; am < 4; am++)
        #pragma unroll
        for (int bn = 0; bn < 4; bn++)
            mma16816(c[am][bn], a[am], b[bn]);
}

// full 3-term stage (reduce/xxt): (Ah,Bh), (Ah,Bl), (Al,Bh)
__device__ __forceinline__ void stage_compute(uint32_t sb, int wm, int wn,
                                              int lane, float c[4][4][4]) {
    uint32_t Ah = sb + wm * TROW,            Al = Ah + TILE_B;
    uint32_t Bh = sb + 2 * TILE_B + wn * TROW, Bl = Bh + TILE_B;
    #pragma unroll
    for (int kk = 0; kk < 32; kk += 16) {
        mma_k16(Ah, Bh, kk, lane, c);
        mma_k16(Ah, Bl, kk, lane, c);
        mma_k16(Al, Bh, kk, lane, c);
    }
}
// 2-term stage (ygemm/conv): (Ah + Al) x Bh
__device__ __forceinline__ void stage_compute_2A(uint32_t sb, int wm, int wn,
                                                 int lane, float c[4][4][4]) {
    uint32_t Ah = sb + wm * TROW, Al = Ah + TILE_B;
    uint32_t Bh = sb + 2 * TILE_B + wn * TROW;
    #pragma unroll
    for (int kk = 0; kk < 32; kk += 16) mma_k16_2A(Ah, Al, Bh, kk, lane, c);
}

#define GEMM_VARS()                                                            \
    extern __shared__ __align__(16) char dsm[];                                \
    uint32_t sb0 = smem_u32(dsm);                                              \
    int tid = threadIdx.x, wid = tid >> 5, lane = tid & 31;                    \
    int wm = (wid >> 2) * 64, wn = (wid & 3) * 32;                             \
    float c[4][4][4] = {};

// ---------------- small prep kernels ----------------------------------------
__global__ void k_zero() {
    g_zsum[blockIdx.x * blockDim.x + threadIdx.x] = 0.f;
}
__global__ void prep_bn(const float* __restrict__ rb, const float* __restrict__ rg,
                        const float* __restrict__ rbe, const float* __restrict__ rm,
                        const float* __restrict__ rv,
                        const float* __restrict__ cb, const float* __restrict__ cg,
                        const float* __restrict__ cbe, const float* __restrict__ cm,
                        const float* __restrict__ cv) {
    int i = blockIdx.x * blockDim.x + threadIdx.x;
    if (i < CMID) {
        float inv = rg[i] * rsqrtf(rv[i] + EPS);
        g_scale1[i] = inv;
        g_shift1[i] = (rb[i] - rm[i]) * inv + rbe[i];
        float inv3 = cg[i] * rsqrtf(cv[i] + EPS);
        g_scale3[i] = inv3;
        g_shift3[i] = (cb[i] - cm[i]) * inv3 + cbe[i];
    }
}
__global__ void cvt_w1(const float* __restrict__ w) {
    int i = blockIdx.x * blockDim.x + threadIdx.x;
    __nv_bfloat16 hi, lo; split_bf16(w[i], hi, lo);
    g_w1_h[i] = hi; g_w1_l[i] = lo;
}
__global__ void cvt_w3(const float* __restrict__ w) {
    int i = blockIdx.x * blockDim.x + threadIdx.x;   // over 512*4608
    int o = i / K33, k = i - o * K33;
    int rs = k >> 9, cc = k & 511;
    int r = rs / 3, s = rs - r * 3;
    float v = w[((o * CMID + cc) * 3 + r) * 3 + s];
    __nv_bfloat16 hi, lo; split_bf16(v, hi, lo);
    g_w3_h[i] = hi; g_w3_l[i] = lo;
}
// transpose + split features: F[b][c][hw] -> g_fT[b*196+hw][c]
__global__ void cvt_f(const float* __restrict__ f2, const float* __restrict__ f3) {
    __shared__ float t[32][33];
    int hw0 = blockIdx.x * 32, c0 = blockIdx.y * 32, b = blockIdx.z;
    const float* F = (b < HB) ? f2 + (size_t)b * CIN * HW
                              : f3 + (size_t)(b - HB) * CIN * HW;
    int tx = threadIdx.x, ty = threadIdx.y;
    #pragma unroll
    for (int k = 0; k < 4; k++) {
        int cc = c0 + ty + k * 8, hw = hw0 + tx;
        t[ty + k * 8][tx] = (hw < HW) ? F[(size_t)cc * HW + hw] : 0.f;
    }
    __syncthreads();
    #pragma unroll
    for (int k = 0; k < 4; k++) {
        int hw = hw0 + ty + k * 8;
        if (hw < HW) {
            float v = t[tx][ty + k * 8];
            __nv_bfloat16 hi, lo; split_bf16(v, hi, lo);
            size_t idx = ((size_t)b * HW + hw) * CIN + c0 + tx;
            g_fT_h[idx] = hi; g_fT_l[idx] = lo;
        }
    }
}
// bf16 transpose device helper: src [b][c][HWP] -> dst [b][hw][CMID]
__device__ __forceinline__ void bt_body(const __nv_bfloat16* __restrict__ src,
                                        __nv_bfloat16* __restrict__ dst) {
    __shared__ __nv_bfloat16 t[32][33];
    int hw0 = blockIdx.x * 32, c0 = blockIdx.y * 32, b = blockIdx.z;
    int tx = threadIdx.x, ty = threadIdx.y;
    const __nv_bfloat16* S = src + (size_t)b * CMID * HWP;
    #pragma unroll
    for (int k = 0; k < 4; k++)
        t[ty + k * 8][tx] = S[(size_t)(c0 + ty + k * 8) * HWP + hw0 + tx];
    __syncthreads();
    #pragma unroll
    for (int k = 0; k < 4; k++) {
        int hw = hw0 + ty + k * 8;
        if (hw < HW)
            dst[((size_t)b * HW + hw) * CMID + c0 + tx] = t[tx][ty + k * 8];
    }
}
// globals bound in DEVICE code (host cannot take &__device__ symbols)
__global__ void k_btx() { bt_body(g_x_h, g_xT_h); }
__global__ void k_bty() { bt_body(g_y_ch, g_yT_h); }

// ---------------- K1: reduce GEMM (M=512, N=25088, K=2048) + BN/ReLU --------
// grid (4 m, 196 n): m fastest -> 4 consecutive CTAs share each B tile in L2
__global__ __launch_bounds__(256, 2) void k_reduce_mma() {
    GEMM_VARS();
    int m0 = blockIdx.x * 128, n0 = blockIdx.y * 128;
    const int T = CIN / 32;    // 64 stages
    const __nv_bfloat16* Awh = g_w1_h + (size_t)m0 * CIN;
    const __nv_bfloat16* Awl = g_w1_l + (size_t)m0 * CIN;
    const __nv_bfloat16* Bfh = g_fT_h + (size_t)n0 * CIN;
    const __nv_bfloat16* Bfl = g_fT_l + (size_t)n0 * CIN;
    #define ISSUE(kt) {                                                        \
        uint32_t s = sb0 + ((kt) & 1) * STAGE_B; int k0 = (kt) * 32;           \
        cpa_tile(s,              Awh, CIN, k0, tid);                           \
        cpa_tile(s + TILE_B,     Awl, CIN, k0, tid);                           \
        cpa_tile(s + 2 * TILE_B, Bfh, CIN, k0, tid);                           \
        cpa_tile(s + 3 * TILE_B, Bfl, CIN, k0, tid); }
    ISSUE(0); cp_commit();
    for (int kt = 0; kt < T; kt++) {
        if (kt + 1 < T) { ISSUE(kt + 1); cp_commit(); cp_wait<1>(); }
        else cp_wait<0>();
        __syncthreads();
        stage_compute(sb0 + (kt & 1) * STAGE_B, wm, wn, lane, c);
        __syncthreads();
    }
    #undef ISSUE
    #pragma unroll
    for (int am = 0; am < 4; am++) {
        #pragma unroll
        for (int half = 0; half < 2; half++) {
            int o = m0 + wm + am * 16 + (lane >> 2) + half * 8;
            float sc = g_scale1[o], sh = g_shift1[o];
            #pragma unroll
            for (int bn = 0; bn < 4; bn++) {
                #pragma unroll
                for (int e = 0; e < 2; e++) {
                    float v = c[am][bn][half * 2 + e];
                    v = fmaxf(v * sc + sh, 0.f);
                    int col = n0 + wn + bn * 8 + 2 * (lane & 3) + e;
                    int b = col / HW, hw = col - b * HW;
                    __nv_bfloat16 hi, lo; split_bf16(v, hi, lo);
                    size_t i1 = ((size_t)b * CMID + o) * HWP + hw;
                    g_x_h[i1] = hi; g_x_l[i1] = lo;
                }
            }
        }
    }
}

// ---------------- K2: XXt per batch (M=N=512, K=196 pad 224) ----------------
__global__ __launch_bounds__(256, 2) void k_xxt_mma() {
    GEMM_VARS();
    int n0 = blockIdx.x * 128, m0 = blockIdx.y * 128, b = blockIdx.z;
    const __nv_bfloat16* Xh = g_x_h + (size_t)b * CMID * HWP;
    const __nv_bfloat16* Xl = g_x_l + (size_t)b * CMID * HWP;
    const int T = KXT / 32;    // 7 stages
    #define ISSUE(kt) {                                                        \
        uint32_t s = sb0 + ((kt) & 1) * STAGE_B; int k0 = (kt) * 32;           \
        cpa_tile(s,              Xh + (size_t)m0 * HWP, HWP, k0, tid);         \
        cpa_tile(s + TILE_B,     Xl + (size_t)m0 * HWP, HWP, k0, tid);         \
        cpa_tile(s + 2 * TILE_B, Xh + (size_t)n0 * HWP, HWP, k0, tid);         \
        cpa_tile(s + 3 * TILE_B, Xl + (size_t)n0 * HWP, HWP, k0, tid); }
    ISSUE(0); cp_commit();
    for (int kt = 0; kt < T; kt++) {
        if (kt + 1 < T) { ISSUE(kt + 1); cp_commit(); cp_wait<1>(); }
        else cp_wait<0>();
        __syncthreads();
        stage_compute(sb0 + (kt & 1) * STAGE_B, wm, wn, lane, c);
        __syncthreads();
    }
    #undef ISSUE
    float* out = g_att + (size_t)b * CMID * CMID;
    #pragma unroll
    for (int am = 0; am < 4; am++)
        #pragma unroll
        for (int half = 0; half < 2; half++) {
            int r = m0 + wm + am * 16 + (lane >> 2) + half * 8;
            #pragma unroll
            for (int bn = 0; bn < 4; bn++) {
                int col = n0 + wn + bn * 8 + 2 * (lane & 3);
                out[(size_t)r * CMID + col]     = c[am][bn][half * 2 + 0];
                out[(size_t)r * CMID + col + 1] = c[am][bn][half * 2 + 1];
            }
        }
}

// ---------------- K3: softmax(-S) rowwise -> bf16 hi/lo ---------------------
__global__ __launch_bounds__(256) void k_softmax() {
    int gw = (blockIdx.x * blockDim.x + threadIdx.x) >> 5;
    int lane = threadIdx.x & 31;
    if (gw >= BATCH * CMID) return;
    const float* row = g_att + (size_t)gw * CMID;
    float mn = CUDART_INF_F;
    #pragma unroll
    for (int t = 0; t < 16; t++) mn = fminf(mn, row[lane + t * 32]);
    #pragma unroll
    for (int o = 16; o; o >>= 1) mn = fminf(mn, __shfl_xor_sync(~0u, mn, o));
    float e[16], sum = 0.f;
    #pragma unroll
    for (int t = 0; t < 16; t++) { e[t] = __expf(mn - row[lane + t * 32]); sum += e[t]; }
    #pragma unroll
    for (int o = 16; o; o >>= 1) sum += __shfl_xor_sync(~0u, sum, o);
    float inv = 1.f / sum;
    #pragma unroll
    for (int t = 0; t < 16; t++) {
        float v = e[t] * inv;
        __nv_bfloat16 hi, lo; split_bf16(v, hi, lo);
        size_t i = (size_t)gw * CMID + lane + t * 32;
        g_att_h[i] = hi; g_att_l[i] = lo;
    }
}

// ---------------- K4: y = att @ X (M=512, N=196pad256, K=512), 2-term -------
__global__ __launch_bounds__(256, 2) void k_ygemm_mma() {
    GEMM_VARS();
    int n0 = blockIdx.x * 128, m0 = blockIdx.y * 128, b = blockIdx.z;
    const __nv_bfloat16* Ah = g_att_h + ((size_t)b * CMID + m0) * CMID;
    const __nv_bfloat16* Al = g_att_l + ((size_t)b * CMID + m0) * CMID;
    const __nv_bfloat16* Bh = g_xT_h + (size_t)b * HW * CMID;
    const int T = CMID / 32;   // 16 stages
    #define ISSUE(kt) {                                                        \
        uint32_t s = sb0 + ((kt) & 1) * STAGE3_B; int k0 = (kt) * 32;          \
        cpa_tile(s,          Ah, CMID, k0, tid);                               \
        cpa_tile(s + TILE_B, Al, CMID, k0, tid);                               \
        cpa_tile_clamp(s + 2 * TILE_B, Bh, CMID, n0, HW - 1, k0, tid); }
    ISSUE(0); cp_commit();
    for (int kt = 0; kt < T; kt++) {
        if (kt + 1 < T) { ISSUE(kt + 1); cp_commit(); cp_wait<1>(); }
        else cp_wait<0>();
        __syncthreads();
        stage_compute_2A(sb0 + (kt & 1) * STAGE3_B, wm, wn, lane, c);
        __syncthreads();
    }
    #undef ISSUE
    // coalesced write: y in [b][i(c)][col(hw)] layout, HWP stride (pad ok)
    __nv_bfloat16* Y = g_y_ch + (size_t)b * CMID * HWP;
    #pragma unroll
    for (int am = 0; am < 4; am++)
        #pragma unroll
        for (int half = 0; half < 2; half++) {
            int i = m0 + wm + am * 16 + (lane >> 2) + half * 8;
            #pragma unroll
            for (int bn = 0; bn < 4; bn++) {
                int col = n0 + wn + bn * 8 + 2 * (lane & 3);
                __nv_bfloat162 p;
                p.x = __float2bfloat16(c[am][bn][half * 2 + 0]);
                p.y = __float2bfloat16(c[am][bn][half * 2 + 1]);
                *reinterpret_cast<__nv_bfloat162*>(&Y[(size_t)i * HWP + col]) = p;
            }
        }
}

// ---------------- K5: conv3 implicit GEMM (M=512, N=25088, K=4608), 2-term --
// grid (4 m, 196 n). 3-stage pipeline. K reordered (rs, c).
__global__ __launch_bounds__(256, 2) void k_conv_mma() {
    GEMM_VARS();
    int m0 = blockIdx.x * 128, n0 = blockIdx.y * 128;
    const int T = K33 / 32;    // 144 stages
    int gr[2], gb[2], gph[2], gpw[2];
    #pragma unroll
    for (int it = 0; it < 2; it++) {
        int row = it * 64 + (tid >> 2);
        gr[it] = row;
        int col = n0 + row;
        gb[it] = col / HW;
        int p = col - gb[it] * HW;
        gph[it] = p / 14; gpw[it] = p - gph[it] * 14;
    }
    int seg = tid & 3;
    #define ISSUE(kt) {                                                        \
        uint32_t s = sb0 + ((kt) % 3) * STAGE3_B; int k0 = (kt) * 32;          \
        cpa_tile(s,          g_w3_h + (size_t)m0 * K33, K33, k0, tid);         \
        cpa_tile(s + TILE_B, g_w3_l + (size_t)m0 * K33, K33, k0, tid);         \
        int rs = (kt) >> 4, c0 = ((kt) & 15) * 32;                             \
        int dr = rs / 3 - 1, ds = rs - (rs / 3) * 3 - 1;                       \
        _Pragma("unroll")                                                      \
        for (int it = 0; it < 2; it++) {                                       \
            int ih = gph[it] + dr, iw = gpw[it] + ds;                          \
            int ok = ((unsigned)ih < 14u) && ((unsigned)iw < 14u);             \
            size_t pix = (size_t)gb[it] * HW + (ok ? ih * 14 + iw : 0);        \
            size_t gidx = pix * CMID + c0 + seg * 8;                           \
            cp16z(s + 2 * TILE_B + gr[it] * TROW + seg * 16, g_yT_h + gidx, ok); \
        } }
    ISSUE(0); cp_commit();
    ISSUE(1); cp_commit();
    for (int kt = 0; kt < T; kt++) {
        if (kt + 2 < T) { ISSUE(kt + 2); cp_commit(); cp_wait<2>(); }
        else if (kt + 1 < T) cp_wait<1>();
        else cp_wait<0>();
        __syncthreads();
        stage_compute_2A(sb0 + (kt % 3) * STAGE3_B, wm, wn, lane, c);
        __syncthreads();
    }
    #undef ISSUE
    // fused BN + ReLU + GAP
    int b0 = n0 / HW;
    int split = (b0 + 1) * HW - n0;   // local cols < split belong to b0
    #pragma unroll
    for (int am = 0; am < 4; am++)
        #pragma unroll
        for (int half = 0; half < 2; half++) {
            int o = m0 + wm + am * 16 + (lane >> 2) + half * 8;
            float sc = g_scale3[o], sh = g_shift3[o];
            float s0 = 0.f, s1 = 0.f;
            #pragma unroll
            for (int bn = 0; bn < 4; bn++)
                #pragma unroll
                for (int e = 0; e < 2; e++) {
                    float v = fmaxf(c[am][bn][half * 2 + e] * sc + sh, 0.f);
                    int lcol = wn + bn * 8 + 2 * (lane & 3) + e;
                    if (lcol < split) s0 += v; else s1 += v;
                }
            s0 += __shfl_xor_sync(~0u, s0, 1);
            s0 += __shfl_xor_sync(~0u, s0, 2);
            s1 += __shfl_xor_sync(~0u, s1, 1);
            s1 += __shfl_xor_sync(~0u, s1, 2);
            if ((lane & 3) == 0) {
                atomicAdd(&g_zsum[b0 * CMID + o], s0 * (1.f / HW));
                if (split < 128)
                    atomicAdd(&g_zsum[(b0 + 1) * CMID + o], s1 * (1.f / HW));
            }
        }
}

// ---------------- K7: fc1 + ReLU --------------------------------------------
__global__ __launch_bounds__(256) void k_fc1(const float* __restrict__ w,
                                             const float* __restrict__ bias) {
    int gw = (blockIdx.x * blockDim.x + threadIdx.x) >> 5;
    int lane = threadIdx.x & 31;
    if (gw >= BATCH * 200) return;
    int b = gw / 200, j = gw - b * 200;
    const float* zr = g_zsum + b * CMID;
    const float* wr = w + (size_t)j * CMID;
    float s = 0.f;
    for (int k = lane; k < CMID; k += 32) s += zr[k] * wr[k];
    #pragma unroll
    for (int o = 16; o; o >>= 1) s += __shfl_xor_sync(~0u, s, o);
    if (lane == 0) g_h[gw] = fmaxf(s + bias[j], 0.f);
}

// ---------------- K8: fc2 + branch-sum --------------------------------------
__global__ __launch_bounds__(256) void k_fc2(const float* __restrict__ w,
                                             const float* __restrict__ bias,
                                             float* __restrict__ out) {
    int gw = (blockIdx.x * blockDim.x + threadIdx.x) >> 5;
    int lane = threadIdx.x & 31;
    if (gw >= HB * 200) return;
    int b = gw / 200, j = gw - b * 200;
    const float* h1 = g_h + (size_t)b * 200;
    const float* h2 = g_h + (size_t)(b + HB) * 200;
    const float* wr = w + (size_t)j * 200;
    float s = 0.f;
    for (int k = lane; k < 200; k += 32) s += (h1[k] + h2[k]) * wr[k];
    #pragma unroll
    for (int o = 16; o; o >>= 1) s += __shfl_xor_sync(~0u, s, o);
    if (lane == 0) out[gw] = s + 2.f * bias[j];
}

// ---------------- launch ----------------------------------------------------
extern "C" void kernel_launch(void* const* d_in, const int* in_sizes, int n_in,
                              void* d_out, int out_size) {
    const float* f2  = (const float*)d_in[0];
    const float* f3  = (const float*)d_in[1];
    const float* rw  = (const float*)d_in[2];
    const float* rb  = (const float*)d_in[3];
    const float* rg  = (const float*)d_in[4];
    const float* rbe = (const float*)d_in[5];
    const float* rm  = (const float*)d_in[6];
    const float* rv  = (const float*)d_in[7];
    const float* c3w = (const float*)d_in[8];
    const float* c3b = (const float*)d_in[9];
    const float* c3g = (const float*)d_in[10];
    const float* c3be= (const float*)d_in[11];
    const float* c3m = (const float*)d_in[12];
    const float* c3v = (const float*)d_in[13];
    const float* f1w = (const float*)d_in[14];
    const float* f1b = (const float*)d_in[15];
    const float* f2w = (const float*)d_in[16];
    const float* f2b = (const float*)d_in[17];
    float* out = (float*)d_out;

    cudaFuncSetAttribute(k_reduce_mma, cudaFuncAttributeMaxDynamicSharedMemorySize, DYN_SMEM);
    cudaFuncSetAttribute(k_xxt_mma,    cudaFuncAttributeMaxDynamicSharedMemorySize, DYN_SMEM);
    cudaFuncSetAttribute(k_ygemm_mma,  cudaFuncAttributeMaxDynamicSharedMemorySize, DYN3B_SMEM);
    cudaFuncSetAttribute(k_conv_mma,   cudaFuncAttributeMaxDynamicSharedMemorySize, DYN3_SMEM);

    k_zero<<<BATCH * CMID / 256, 256>>>();
    prep_bn<<<2, 256>>>(rb, rg, rbe, rm, rv, c3b, c3g, c3be, c3m, c3v);
    cvt_w1<<<(CMID * CIN) / 256, 256>>>(rw);
    cvt_w3<<<(CMID * K33) / 256, 256>>>(c3w);
    cvt_f<<<dim3(7, CIN / 32, BATCH), dim3(32, 8)>>>(f2, f3);

    k_reduce_mma<<<dim3(4, NFLAT / 128), 256, DYN_SMEM>>>();
    k_btx<<<dim3(7, CMID / 32, BATCH), dim3(32, 8)>>>();  // x^T
    k_xxt_mma<<<dim3(4, 4, BATCH), 256, DYN_SMEM>>>();
    k_softmax<<<(BATCH * CMID) / 8, 256>>>();
    k_ygemm_mma<<<dim3(2, 4, BATCH), 256, DYN3B_SMEM>>>();
    k_bty<<<dim3(7, CMID / 32, BATCH), dim3(32, 8)>>>();  // y^T
    k_conv_mma<<<dim3(4, NFLAT / 128), 256, DYN3_SMEM>>>();
    k_fc1<<<(BATCH * 200 + 7) / 8, 256>>>(f1w, f1b);
    k_fc2<<<(HB * 200 + 7) / 8, 256>>>(f2w, f2b, out);
}

// round 11
// speedup vs baseline: 1.0121x; 1.0121x over previous
#include <cuda_runtime.h>
#include <cuda_bf16.h>
#include <cstdint>
#include <math_constants.h>

#define EPS 1e-5f
#define HB 64
#define BATCH 128
#define CIN 2048
#define CMID 512
#define HW 196
#define HWP 256
#define KXT 224     // xxt effective K (>=196, /32)
#define K33 4608
#define NFLAT 25088   // 128*196 = 196 tiles of 128 exactly

// ---------------- scratch (static device globals; zero-init at load) --------
__device__ __nv_bfloat16 g_fT_h[(size_t)NFLAT * CIN];
__device__ __nv_bfloat16 g_fT_l[(size_t)NFLAT * CIN];
__device__ __nv_bfloat16 g_x_h [(size_t)BATCH * CMID * HWP];  // pad cols stay 0
__device__ __nv_bfloat16 g_x_l [(size_t)BATCH * CMID * HWP];
__device__ __nv_bfloat16 g_xT_h[(size_t)BATCH * HW * CMID];
__device__ float         g_att [(size_t)BATCH * CMID * CMID];
__device__ __nv_bfloat16 g_att_h[(size_t)BATCH * CMID * CMID];
__device__ __nv_bfloat16 g_att_l[(size_t)BATCH * CMID * CMID];
__device__ __nv_bfloat16 g_yT_h[(size_t)BATCH * HW * CMID];
__device__ __nv_bfloat16 g_w1_h[(size_t)CMID * CIN];
__device__ __nv_bfloat16 g_w1_l[(size_t)CMID * CIN];
__device__ __nv_bfloat16 g_w3_h[(size_t)CMID * K33];   // reordered k = rs*512 + c
__device__ __nv_bfloat16 g_w3_l[(size_t)CMID * K33];
__device__ float g_zsum[BATCH * CMID];
__device__ float g_h[BATCH * 200];
__device__ float g_scale1[CMID], g_shift1[CMID], g_scale3[CMID], g_shift3[CMID];

// ---------------- ptx helpers (all non-'a' gated: sm_80-level) --------------
__device__ __forceinline__ uint32_t smem_u32(const void* p) {
    uint32_t a;
    asm("{ .reg .u64 t; cvta.to.shared.u64 t, %1; cvt.u32.u64 %0, t; }"
        : "=r"(a) : "l"(p));
    return a;
}
__device__ __forceinline__ void cp16(uint32_t dst, const void* src) {
    asm volatile("cp.async.ca.shared.global [%0], [%1], 16;"
                 :: "r"(dst), "l"(src));
}
__device__ __forceinline__ void cp16z(uint32_t dst, const void* src, int ok) {
    int sz = ok ? 16 : 0;
    asm volatile("cp.async.ca.shared.global [%0], [%1], 16, %2;"
                 :: "r"(dst), "l"(src), "r"(sz));
}
__device__ __forceinline__ void cp_commit() {
    asm volatile("cp.async.commit_group;" ::: "memory");
}
template<int N> __device__ __forceinline__ void cp_wait() {
    asm volatile("cp.async.wait_group %0;" :: "n"(N) : "memory");
}
__device__ __forceinline__ void ldm4(uint32_t* r, uint32_t addr) {
    asm volatile("ldmatrix.sync.aligned.m8n8.x4.shared.b16 {%0,%1,%2,%3}, [%4];"
                 : "=r"(r[0]), "=r"(r[1]), "=r"(r[2]), "=r"(r[3]) : "r"(addr));
}
__device__ __forceinline__ void ldm2(uint32_t* r, uint32_t addr) {
    asm volatile("ldmatrix.sync.aligned.m8n8.x2.shared.b16 {%0,%1}, [%2];"
                 : "=r"(r[0]), "=r"(r[1]) : "r"(addr));
}
__device__ __forceinline__ void mma16816(float* c, const uint32_t* a,
                                         const uint32_t* b) {
    asm volatile(
        "mma.sync.aligned.m16n8k16.row.col.f32.bf16.bf16.f32 "
        "{%0,%1,%2,%3}, {%4,%5,%6,%7}, {%8,%9}, {%0,%1,%2,%3};"
        : "+f"(c[0]), "+f"(c[1]), "+f"(c[2]), "+f"(c[3])
        : "r"(a[0]), "r"(a[1]), "r"(a[2]), "r"(a[3]), "r"(b[0]), "r"(b[1]));
}
__device__ __forceinline__ void split_bf16(float v, __nv_bfloat16& hi,
                                           __nv_bfloat16& lo) {
    hi = __float2bfloat16(v);
    lo = __float2bfloat16(v - __bfloat162float(hi));
}

// ---------------- SMEM geometry ---------------------------------------------
#define TROW 80
#define TILE_B (128 * TROW)          // 10240 B
#define STAGE_B (4 * TILE_B)         // Ah, Al, Bh, Bl (reduce/xxt)
#define STAGE3_B (3 * TILE_B)        // Ah, Al, Bh     (ygemm/conv)
#define DYN_SMEM (2 * STAGE_B)       // 81920 B
#define DYN3_SMEM (3 * STAGE3_B)     // 92160 B (conv, 3-stage)
#define DYN3B_SMEM (2 * STAGE3_B)    // 61440 B (ygemm, 2-stage)

// contiguous 128x32 tile load via cp.async: 512 16B chunks / 256 threads
__device__ __forceinline__ void cpa_tile(uint32_t sdst, const __nv_bfloat16* g,
                                         size_t stride, int k0, int tid) {
    #pragma unroll
    for (int it = 0; it < 2; it++) {
        int ch = it * 256 + tid;
        int row = ch >> 2, seg = ch & 3;
        cp16(sdst + row * TROW + seg * 16,
             g + (size_t)row * stride + k0 + seg * 8);
    }
}
__device__ __forceinline__ void cpa_tile_clamp(uint32_t sdst,
                                               const __nv_bfloat16* g,
                                               size_t stride, int row0,
                                               int maxrow, int k0, int tid) {
    #pragma unroll
    for (int it = 0; it < 2; it++) {
        int ch = it * 256 + tid;
        int row = ch >> 2, seg = ch & 3;
        int rg = row0 + row; if (rg > maxrow) rg = maxrow;
        cp16(sdst + row * TROW + seg * 16,
             g + (size_t)rg * stride + k0 + seg * 8);
    }
}

// one k16 slab: 4 m-atoms x 4 n-atoms of m16n8k16
__device__ __forceinline__ void mma_k16(uint32_t aBase, uint32_t bBase, int kk,
                                        int lane, float c[4][4][4]) {
    uint32_t a[4][4], b[4][2];
    int arow = lane & 15, asel = lane >> 4;
    #pragma unroll
    for (int am = 0; am < 4; am++)
        ldm4(a[am], aBase + (am * 16 + arow) * TROW + (kk + asel * 8) * 2);
    int brow = lane & 7, bsel = (lane >> 3) & 1;
    #pragma unroll
    for (int bn = 0; bn < 4; bn++)
        ldm2(b[bn], bBase + (bn * 8 + brow) * TROW + (kk + bsel * 8) * 2);
    #pragma unroll
    for (int am = 0; am < 4; am++)
        #pragma unroll
        for (int bn = 0; bn < 4; bn++)
            mma16816(c[am][bn], a[am], b[bn]);
}

// 2-A variant: (Ahi + Alo) x B, B fragments loaded once
__device__ __forceinline__ void mma_k16_2A(uint32_t aH, uint32_t aL,
                                           uint32_t bBase, int kk, int lane,
                                           float c[4][4][4]) {
    uint32_t a[4][4], b[4][2];
    int arow = lane & 15, asel = lane >> 4;
    int brow = lane & 7, bsel = (lane >> 3) & 1;
    #pragma unroll
    for (int bn = 0; bn < 4; bn++)
        ldm2(b[bn], bBase + (bn * 8 + brow) * TROW + (kk + bsel * 8) * 2);
    #pragma unroll
    for (int am = 0; am < 4; am++)
        ldm4(a[am], aH + (am * 16 + arow) * TROW + (kk + asel * 8) * 2);
    #pragma unroll
    for (int am = 0; am < 4; am++)
        #pragma unroll
        for (int bn = 0; bn < 4; bn++)
            mma16816(c[am][bn], a[am], b[bn]);
    #pragma unroll
    for (int am = 0; am < 4; am++)
        ldm4(a[am], aL + (am * 16 + arow) * TROW + (kk + asel * 8) * 2);
    #pragma unroll
    for (int am = 0; am < 4; am++)
        #pragma unroll
        for (int bn = 0; bn < 4; bn++)
            mma16816(c[am][bn], a[am], b[bn]);
}

// fused 3-term stage (reduce/xxt): load Bh,Bl,Ah once -> (Ah,Bh)+(Ah,Bl),
// then load Al -> (Al,Bh). 16 ldmatrix / 48 MMA per kk (was 30 / 48).
__device__ __forceinline__ void stage_compute_f3(uint32_t sb, int wm, int wn,
                                                 int lane, float c[4][4][4]) {
    uint32_t Ah = sb + wm * TROW,              Al = Ah + TILE_B;
    uint32_t Bh = sb + 2 * TILE_B + wn * TROW, Bl = Bh + TILE_B;
    int arow = lane & 15, asel = lane >> 4;
    int brow = lane & 7,  bsel = (lane >> 3) & 1;
    #pragma unroll
    for (int kk = 0; kk < 32; kk += 16) {
        uint32_t bh[4][2], bl[4][2], a[4][4];
        #pragma unroll
        for (int bn = 0; bn < 4; bn++) {
            ldm2(bh[bn], Bh + (bn * 8 + brow) * TROW + (kk + bsel * 8) * 2);
            ldm2(bl[bn], Bl + (bn * 8 + brow) * TROW + (kk + bsel * 8) * 2);
        }
        #pragma unroll
        for (int am = 0; am < 4; am++)
            ldm4(a[am], Ah + (am * 16 + arow) * TROW + (kk + asel * 8) * 2);
        #pragma unroll
        for (int am = 0; am < 4; am++)
            #pragma unroll
            for (int bn = 0; bn < 4; bn++) {
                mma16816(c[am][bn], a[am], bh[bn]);
                mma16816(c[am][bn], a[am], bl[bn]);
            }
        #pragma unroll
        for (int am = 0; am < 4; am++)
            ldm4(a[am], Al + (am * 16 + arow) * TROW + (kk + asel * 8) * 2);
        #pragma unroll
        for (int am = 0; am < 4; am++)
            #pragma unroll
            for (int bn = 0; bn < 4; bn++)
                mma16816(c[am][bn], a[am], bh[bn]);
    }
}
// 2-term stage (ygemm/conv): (Ah + Al) x Bh
__device__ __forceinline__ void stage_compute_2A(uint32_t sb, int wm, int wn,
                                                 int lane, float c[4][4][4]) {
    uint32_t Ah = sb + wm * TROW, Al = Ah + TILE_B;
    uint32_t Bh = sb + 2 * TILE_B + wn * TROW;
    #pragma unroll
    for (int kk = 0; kk < 32; kk += 16) mma_k16_2A(Ah, Al, Bh, kk, lane, c);
}

#define GEMM_VARS()                                                            \
    extern __shared__ __align__(16) char dsm[];                                \
    uint32_t sb0 = smem_u32(dsm);                                              \
    int tid = threadIdx.x, wid = tid >> 5, lane = tid & 31;                    \
    int wm = (wid >> 2) * 64, wn = (wid & 3) * 32;                             \
    float c[4][4][4] = {};

// ---------------- small prep kernels ----------------------------------------
__global__ void k_zero() {
    g_zsum[blockIdx.x * blockDim.x + threadIdx.x] = 0.f;
}
__global__ void prep_bn(const float* __restrict__ rb, const float* __restrict__ rg,
                        const float* __restrict__ rbe, const float* __restrict__ rm,
                        const float* __restrict__ rv,
                        const float* __restrict__ cb, const float* __restrict__ cg,
                        const float* __restrict__ cbe, const float* __restrict__ cm,
                        const float* __restrict__ cv) {
    int i = blockIdx.x * blockDim.x + threadIdx.x;
    if (i < CMID) {
        float inv = rg[i] * rsqrtf(rv[i] + EPS);
        g_scale1[i] = inv;
        g_shift1[i] = (rb[i] - rm[i]) * inv + rbe[i];
        float inv3 = cg[i] * rsqrtf(cv[i] + EPS);
        g_scale3[i] = inv3;
        g_shift3[i] = (cb[i] - cm[i]) * inv3 + cbe[i];
    }
}
__global__ void cvt_w1(const float* __restrict__ w) {
    int i = blockIdx.x * blockDim.x + threadIdx.x;
    __nv_bfloat16 hi, lo; split_bf16(w[i], hi, lo);
    g_w1_h[i] = hi; g_w1_l[i] = lo;
}
__global__ void cvt_w3(const float* __restrict__ w) {
    int i = blockIdx.x * blockDim.x + threadIdx.x;   // over 512*4608
    int o = i / K33, k = i - o * K33;
    int rs = k >> 9, cc = k & 511;
    int r = rs / 3, s = rs - r * 3;
    float v = w[((o * CMID + cc) * 3 + r) * 3 + s];
    __nv_bfloat16 hi, lo; split_bf16(v, hi, lo);
    g_w3_h[i] = hi; g_w3_l[i] = lo;
}
// transpose + split features: F[b][c][hw] -> g_fT[b*196+hw][c]
__global__ void cvt_f(const float* __restrict__ f2, const float* __restrict__ f3) {
    __shared__ float t[32][33];
    int hw0 = blockIdx.x * 32, c0 = blockIdx.y * 32, b = blockIdx.z;
    const float* F = (b < HB) ? f2 + (size_t)b * CIN * HW
                              : f3 + (size_t)(b - HB) * CIN * HW;
    int tx = threadIdx.x, ty = threadIdx.y;
    #pragma unroll
    for (int k = 0; k < 4; k++) {
        int cc = c0 + ty + k * 8, hw = hw0 + tx;
        t[ty + k * 8][tx] = (hw < HW) ? F[(size_t)cc * HW + hw] : 0.f;
    }
    __syncthreads();
    #pragma unroll
    for (int k = 0; k < 4; k++) {
        int hw = hw0 + ty + k * 8;
        if (hw < HW) {
            float v = t[tx][ty + k * 8];
            __nv_bfloat16 hi, lo; split_bf16(v, hi, lo);
            size_t idx = ((size_t)b * HW + hw) * CIN + c0 + tx;
            g_fT_h[idx] = hi; g_fT_l[idx] = lo;
        }
    }
}

// ---------------- K1: reduce GEMM (M=512, N=25088, K=2048) + BN/ReLU --------
// grid (4 m, 196 n): m fastest -> 4 consecutive CTAs share each B tile in L2
__global__ __launch_bounds__(256, 2) void k_reduce_mma() {
    GEMM_VARS();
    int m0 = blockIdx.x * 128, n0 = blockIdx.y * 128;
    const int T = CIN / 32;    // 64 stages
    const __nv_bfloat16* Awh = g_w1_h + (size_t)m0 * CIN;
    const __nv_bfloat16* Awl = g_w1_l + (size_t)m0 * CIN;
    const __nv_bfloat16* Bfh = g_fT_h + (size_t)n0 * CIN;
    const __nv_bfloat16* Bfl = g_fT_l + (size_t)n0 * CIN;
    #define ISSUE(kt) {                                                        \
        uint32_t s = sb0 + ((kt) & 1) * STAGE_B; int k0 = (kt) * 32;           \
        cpa_tile(s,              Awh, CIN, k0, tid);                           \
        cpa_tile(s + TILE_B,     Awl, CIN, k0, tid);                           \
        cpa_tile(s + 2 * TILE_B, Bfh, CIN, k0, tid);                           \
        cpa_tile(s + 3 * TILE_B, Bfl, CIN, k0, tid); }
    ISSUE(0); cp_commit();
    for (int kt = 0; kt < T; kt++) {
        if (kt + 1 < T) { ISSUE(kt + 1); cp_commit(); cp_wait<1>(); }
        else cp_wait<0>();
        __syncthreads();
        stage_compute_f3(sb0 + (kt & 1) * STAGE_B, wm, wn, lane, c);
        __syncthreads();
    }
    #undef ISSUE
    #pragma unroll
    for (int am = 0; am < 4; am++) {
        #pragma unroll
        for (int half = 0; half < 2; half++) {
            int o = m0 + wm + am * 16 + (lane >> 2) + half * 8;
            float sc = g_scale1[o], sh = g_shift1[o];
            #pragma unroll
            for (int bn = 0; bn < 4; bn++) {
                #pragma unroll
                for (int e = 0; e < 2; e++) {
                    float v = c[am][bn][half * 2 + e];
                    v = fmaxf(v * sc + sh, 0.f);
                    int col = n0 + wn + bn * 8 + 2 * (lane & 3) + e;
                    int b = col / HW, hw = col - b * HW;
                    __nv_bfloat16 hi, lo; split_bf16(v, hi, lo);
                    size_t i1 = ((size_t)b * CMID + o) * HWP + hw;
                    g_x_h[i1] = hi; g_x_l[i1] = lo;
                    g_xT_h[((size_t)b * HW + hw) * CMID + o] = hi;
                }
            }
        }
    }
}

// ---------------- K2: XXt per batch (M=N=512, K=196 pad 224) ----------------
__global__ __launch_bounds__(256, 2) void k_xxt_mma() {
    GEMM_VARS();
    int n0 = blockIdx.x * 128, m0 = blockIdx.y * 128, b = blockIdx.z;
    const __nv_bfloat16* Xh = g_x_h + (size_t)b * CMID * HWP;
    const __nv_bfloat16* Xl = g_x_l + (size_t)b * CMID * HWP;
    const int T = KXT / 32;    // 7 stages
    #define ISSUE(kt) {                                                        \
        uint32_t s = sb0 + ((kt) & 1) * STAGE_B; int k0 = (kt) * 32;           \
        cpa_tile(s,              Xh + (size_t)m0 * HWP, HWP, k0, tid);         \
        cpa_tile(s + TILE_B,     Xl + (size_t)m0 * HWP, HWP, k0, tid);         \
        cpa_tile(s + 2 * TILE_B, Xh + (size_t)n0 * HWP, HWP, k0, tid);         \
        cpa_tile(s + 3 * TILE_B, Xl + (size_t)n0 * HWP, HWP, k0, tid); }
    ISSUE(0); cp_commit();
    for (int kt = 0; kt < T; kt++) {
        if (kt + 1 < T) { ISSUE(kt + 1); cp_commit(); cp_wait<1>(); }
        else cp_wait<0>();
        __syncthreads();
        stage_compute_f3(sb0 + (kt & 1) * STAGE_B, wm, wn, lane, c);
        __syncthreads();
    }
    #undef ISSUE
    float* out = g_att + (size_t)b * CMID * CMID;
    #pragma unroll
    for (int am = 0; am < 4; am++)
        #pragma unroll
        for (int half = 0; half < 2; half++) {
            int r = m0 + wm + am * 16 + (lane >> 2) + half * 8;
            #pragma unroll
            for (int bn = 0; bn < 4; bn++) {
                int col = n0 + wn + bn * 8 + 2 * (lane & 3);
                out[(size_t)r * CMID + col]     = c[am][bn][half * 2 + 0];
                out[(size_t)r * CMID + col + 1] = c[am][bn][half * 2 + 1];
            }
        }
}

// ---------------- K3: softmax(-S) rowwise -> bf16 hi/lo ---------------------
__global__ __launch_bounds__(256) void k_softmax() {
    int gw = (blockIdx.x * blockDim.x + threadIdx.x) >> 5;
    int lane = threadIdx.x & 31;
    if (gw >= BATCH * CMID) return;
    const float* row = g_att + (size_t)gw * CMID;
    float mn = CUDART_INF_F;
    #pragma unroll
    for (int t = 0; t < 16; t++) mn = fminf(mn, row[lane + t * 32]);
    #pragma unroll
    for (int o = 16; o; o >>= 1) mn = fminf(mn, __shfl_xor_sync(~0u, mn, o));
    float e[16], sum = 0.f;
    #pragma unroll
    for (int t = 0; t < 16; t++) { e[t] = __expf(mn - row[lane + t * 32]); sum += e[t]; }
    #pragma unroll
    for (int o = 16; o; o >>= 1) sum += __shfl_xor_sync(~0u, sum, o);
    float inv = 1.f / sum;
    #pragma unroll
    for (int t = 0; t < 16; t++) {
        float v = e[t] * inv;
        __nv_bfloat16 hi, lo; split_bf16(v, hi, lo);
        size_t i = (size_t)gw * CMID + lane + t * 32;
        g_att_h[i] = hi; g_att_l[i] = lo;
    }
}

// ---------------- K4: y = att @ X (M=512, N=196pad256, K=512), 2-term -------
__global__ __launch_bounds__(256, 2) void k_ygemm_mma() {
    GEMM_VARS();
    int n0 = blockIdx.x * 128, m0 = blockIdx.y * 128, b = blockIdx.z;
    const __nv_bfloat16* Ah = g_att_h + ((size_t)b * CMID + m0) * CMID;
    const __nv_bfloat16* Al = g_att_l + ((size_t)b * CMID + m0) * CMID;
    const __nv_bfloat16* Bh = g_xT_h + (size_t)b * HW * CMID;
    const int T = CMID / 32;   // 16 stages
    #define ISSUE(kt) {                                                        \
        uint32_t s = sb0 + ((kt) & 1) * STAGE3_B; int k0 = (kt) * 32;          \
        cpa_tile(s,          Ah, CMID, k0, tid);                               \
        cpa_tile(s + TILE_B, Al, CMID, k0, tid);                               \
        cpa_tile_clamp(s + 2 * TILE_B, Bh, CMID, n0, HW - 1, k0, tid); }
    ISSUE(0); cp_commit();
    for (int kt = 0; kt < T; kt++) {
        if (kt + 1 < T) { ISSUE(kt + 1); cp_commit(); cp_wait<1>(); }
        else cp_wait<0>();
        __syncthreads();
        stage_compute_2A(sb0 + (kt & 1) * STAGE3_B, wm, wn, lane, c);
        __syncthreads();
    }
    #undef ISSUE
    #pragma unroll
    for (int am = 0; am < 4; am++)
        #pragma unroll
        for (int half = 0; half < 2; half++) {
            int i = m0 + wm + am * 16 + (lane >> 2) + half * 8;
            #pragma unroll
            for (int bn = 0; bn < 4; bn++)
                #pragma unroll
                for (int e = 0; e < 2; e++) {
                    int col = n0 + wn + bn * 8 + 2 * (lane & 3) + e;
                    if (col < HW)
                        g_yT_h[((size_t)b * HW + col) * CMID + i] =
                            __float2bfloat16(c[am][bn][half * 2 + e]);
                }
        }
}

// ---------------- K5: conv3 implicit GEMM (M=512, N=25088, K=4608), 2-term --
// grid (4 m, 196 n). 3-stage pipeline. K reordered (rs, c).
__global__ __launch_bounds__(256, 2) void k_conv_mma() {
    GEMM_VARS();
    int m0 = blockIdx.x * 128, n0 = blockIdx.y * 128;
    const int T = K33 / 32;    // 144 stages
    int gr[2], gb[2], gph[2], gpw[2];
    #pragma unroll
    for (int it = 0; it < 2; it++) {
        int row = it * 64 + (tid >> 2);
        gr[it] = row;
        int col = n0 + row;
        gb[it] = col / HW;
        int p = col - gb[it] * HW;
        gph[it] = p / 14; gpw[it] = p - gph[it] * 14;
    }
    int seg = tid & 3;
    #define ISSUE(kt) {                                                        \
        uint32_t s = sb0 + ((kt) % 3) * STAGE3_B; int k0 = (kt) * 32;          \
        cpa_tile(s,          g_w3_h + (size_t)m0 * K33, K33, k0, tid);         \
        cpa_tile(s + TILE_B, g_w3_l + (size_t)m0 * K33, K33, k0, tid);         \
        int rs = (kt) >> 4, c0 = ((kt) & 15) * 32;                             \
        int dr = rs / 3 - 1, ds = rs - (rs / 3) * 3 - 1;                       \
        _Pragma("unroll")                                                      \
        for (int it = 0; it < 2; it++) {                                       \
            int ih = gph[it] + dr, iw = gpw[it] + ds;                          \
            int ok = ((unsigned)ih < 14u) && ((unsigned)iw < 14u);             \
            size_t pix = (size_t)gb[it] * HW + (ok ? ih * 14 + iw : 0);        \
            size_t gidx = pix * CMID + c0 + seg * 8;                           \
            cp16z(s + 2 * TILE_B + gr[it] * TROW + seg * 16, g_yT_h + gidx, ok); \
        } }
    ISSUE(0); cp_commit();
    ISSUE(1); cp_commit();
    for (int kt = 0; kt < T; kt++) {
        if (kt + 2 < T) { ISSUE(kt + 2); cp_commit(); cp_wait<2>(); }
        else if (kt + 1 < T) cp_wait<1>();
        else cp_wait<0>();
        __syncthreads();
        stage_compute_2A(sb0 + (kt % 3) * STAGE3_B, wm, wn, lane, c);
        __syncthreads();
    }
    #undef ISSUE
    // fused BN + ReLU + GAP
    int b0 = n0 / HW;
    int split = (b0 + 1) * HW - n0;   // local cols < split belong to b0
    #pragma unroll
    for (int am = 0; am < 4; am++)
        #pragma unroll
        for (int half = 0; half < 2; half++) {
            int o = m0 + wm + am * 16 + (lane >> 2) + half * 8;
            float sc = g_scale3[o], sh = g_shift3[o];
            float s0 = 0.f, s1 = 0.f;
            #pragma unroll
            for (int bn = 0; bn < 4; bn++)
                #pragma unroll
                for (int e = 0; e < 2; e++) {
                    float v = fmaxf(c[am][bn][half * 2 + e] * sc + sh, 0.f);
                    int lcol = wn + bn * 8 + 2 * (lane & 3) + e;
                    if (lcol < split) s0 += v; else s1 += v;
                }
            s0 += __shfl_xor_sync(~0u, s0, 1);
            s0 += __shfl_xor_sync(~0u, s0, 2);
            s1 += __shfl_xor_sync(~0u, s1, 1);
            s1 += __shfl_xor_sync(~0u, s1, 2);
            if ((lane & 3) == 0) {
                atomicAdd(&g_zsum[b0 * CMID + o], s0 * (1.f / HW));
                if (split < 128)
                    atomicAdd(&g_zsum[(b0 + 1) * CMID + o], s1 * (1.f / HW));
            }
        }
}

// ---------------- K7: fc1 + ReLU --------------------------------------------
__global__ __launch_bounds__(256) void k_fc1(const float* __restrict__ w,
                                             const float* __restrict__ bias) {
    int gw = (blockIdx.x * blockDim.x + threadIdx.x) >> 5;
    int lane = threadIdx.x & 31;
    if (gw >= BATCH * 200) return;
    int b = gw / 200, j = gw - b * 200;
    const float* zr = g_zsum + b * CMID;
    const float* wr = w + (size_t)j * CMID;
    float s = 0.f;
    for (int k = lane; k < CMID; k += 32) s += zr[k] * wr[k];
    #pragma unroll
    for (int o = 16; o; o >>= 1) s += __shfl_xor_sync(~0u, s, o);
    if (lane == 0) g_h[gw] = fmaxf(s + bias[j], 0.f);
}

// ---------------- K8: fc2 + branch-sum --------------------------------------
__global__ __launch_bounds__(256) void k_fc2(const float* __restrict__ w,
                                             const float* __restrict__ bias,
                                             float* __restrict__ out) {
    int gw = (blockIdx.x * blockDim.x + threadIdx.x) >> 5;
    int lane = threadIdx.x & 31;
    if (gw >= HB * 200) return;
    int b = gw / 200, j = gw - b * 200;
    const float* h1 = g_h + (size_t)b * 200;
    const float* h2 = g_h + (size_t)(b + HB) * 200;
    const float* wr = w + (size_t)j * 200;
    float s = 0.f;
    for (int k = lane; k < 200; k += 32) s += (h1[k] + h2[k]) * wr[k];
    #pragma unroll
    for (int o = 16; o; o >>= 1) s += __shfl_xor_sync(~0u, s, o);
    if (lane == 0) out[gw] = s + 2.f * bias[j];
}

// ---------------- launch ----------------------------------------------------
extern "C" void kernel_launch(void* const* d_in, const int* in_sizes, int n_in,
                              void* d_out, int out_size) {
    const float* f2  = (const float*)d_in[0];
    const float* f3  = (const float*)d_in[1];
    const float* rw  = (const float*)d_in[2];
    const float* rb  = (const float*)d_in[3];
    const float* rg  = (const float*)d_in[4];
    const float* rbe = (const float*)d_in[5];
    const float* rm  = (const float*)d_in[6];
    const float* rv  = (const float*)d_in[7];
    const float* c3w = (const float*)d_in[8];
    const float* c3b = (const float*)d_in[9];
    const float* c3g = (const float*)d_in[10];
    const float* c3be= (const float*)d_in[11];
    const float* c3m = (const float*)d_in[12];
    const float* c3v = (const float*)d_in[13];
    const float* f1w = (const float*)d_in[14];
    const float* f1b = (const float*)d_in[15];
    const float* f2w = (const float*)d_in[16];
    const float* f2b = (const float*)d_in[17];
    float* out = (float*)d_out;

    cudaFuncSetAttribute(k_reduce_mma, cudaFuncAttributeMaxDynamicSharedMemorySize, DYN_SMEM);
    cudaFuncSetAttribute(k_xxt_mma,    cudaFuncAttributeMaxDynamicSharedMemorySize, DYN_SMEM);
    cudaFuncSetAttribute(k_ygemm_mma,  cudaFuncAttributeMaxDynamicSharedMemorySize, DYN3B_SMEM);
    cudaFuncSetAttribute(k_conv_mma,   cudaFuncAttributeMaxDynamicSharedMemorySize, DYN3_SMEM);

    k_zero<<<BATCH * CMID / 256, 256>>>();
    prep_bn<<<2, 256>>>(rb, rg, rbe, rm, rv, c3b, c3g, c3be, c3m, c3v);
    cvt_w1<<<(CMID * CIN) / 256, 256>>>(rw);
    cvt_w3<<<(CMID * K33) / 256, 256>>>(c3w);
    cvt_f<<<dim3(7, CIN / 32, BATCH), dim3(32, 8)>>>(f2, f3);

    k_reduce_mma<<<dim3(4, NFLAT / 128), 256, DYN_SMEM>>>();
    k_xxt_mma<<<dim3(4, 4, BATCH), 256, DYN_SMEM>>>();
    k_softmax<<<(BATCH * CMID) / 8, 256>>>();
    k_ygemm_mma<<<dim3(2, 4, BATCH), 256, DYN3B_SMEM>>>();
    k_conv_mma<<<dim3(4, NFLAT / 128), 256, DYN3_SMEM>>>();
    k_fc1<<<(BATCH * 200 + 7) / 8, 256>>>(f1w, f1b);
    k_fc2<<<(HB * 200 + 7) / 8, 256>>>(f2w, f2b, out);
}

// round 12
// speedup vs baseline: 1.3396x; 1.3236x over previous
#include <cuda_runtime.h>
#include <cuda_fp16.h>
#include <cstdint>
#include <math_constants.h>

#define EPS 1e-5f
#define HB 64
#define BATCH 128
#define CIN 2048
#define CMID 512
#define HW 196
#define HWP 256
#define KXT 224     // xxt effective K (>=196, /32)
#define K33 4608
#define NFLAT 25088   // 128*196 = 196 tiles of 128 exactly

// ---------------- scratch (static device globals; zero-init at load) --------
__device__ __half g_fT_h[(size_t)NFLAT * CIN];
__device__ __half g_fT_l[(size_t)NFLAT * CIN];
__device__ __half g_x_h [(size_t)BATCH * CMID * HWP];  // pad cols stay 0
__device__ __half g_x_l [(size_t)BATCH * CMID * HWP];
__device__ __half g_xT_h[(size_t)BATCH * HW * CMID];
__device__ float  g_att [(size_t)BATCH * CMID * CMID];
__device__ __half g_att_h[(size_t)BATCH * CMID * CMID];
__device__ __half g_yT_h[(size_t)BATCH * HW * CMID];
__device__ __half g_w1_h[(size_t)CMID * CIN];
__device__ __half g_w1_l[(size_t)CMID * CIN];
__device__ __half g_w3_h[(size_t)CMID * K33];   // reordered k = rs*512 + c
__device__ float g_zsum[BATCH * CMID];
__device__ float g_h[BATCH * 200];
__device__ float g_scale1[CMID], g_shift1[CMID], g_scale3[CMID], g_shift3[CMID];

// ---------------- ptx helpers (all non-'a' gated: sm_80-level) --------------
__device__ __forceinline__ uint32_t smem_u32(const void* p) {
    uint32_t a;
    asm("{ .reg .u64 t; cvta.to.shared.u64 t, %1; cvt.u32.u64 %0, t; }"
        : "=r"(a) : "l"(p));
    return a;
}
__device__ __forceinline__ void cp16(uint32_t dst, const void* src) {
    asm volatile("cp.async.ca.shared.global [%0], [%1], 16;"
                 :: "r"(dst), "l"(src));
}
__device__ __forceinline__ void cp16z(uint32_t dst, const void* src, int ok) {
    int sz = ok ? 16 : 0;
    asm volatile("cp.async.ca.shared.global [%0], [%1], 16, %2;"
                 :: "r"(dst), "l"(src), "r"(sz));
}
__device__ __forceinline__ void cp_commit() {
    asm volatile("cp.async.commit_group;" ::: "memory");
}
template<int N> __device__ __forceinline__ void cp_wait() {
    asm volatile("cp.async.wait_group %0;" :: "n"(N) : "memory");
}
__device__ __forceinline__ void ldm4(uint32_t* r, uint32_t addr) {
    asm volatile("ldmatrix.sync.aligned.m8n8.x4.shared.b16 {%0,%1,%2,%3}, [%4];"
                 : "=r"(r[0]), "=r"(r[1]), "=r"(r[2]), "=r"(r[3]) : "r"(addr));
}
__device__ __forceinline__ void ldm2(uint32_t* r, uint32_t addr) {
    asm volatile("ldmatrix.sync.aligned.m8n8.x2.shared.b16 {%0,%1}, [%2];"
                 : "=r"(r[0]), "=r"(r[1]) : "r"(addr));
}
__device__ __forceinline__ void mma16816(float* c, const uint32_t* a,
                                         const uint32_t* b) {
    asm volatile(
        "mma.sync.aligned.m16n8k16.row.col.f32.f16.f16.f32 "
        "{%0,%1,%2,%3}, {%4,%5,%6,%7}, {%8,%9}, {%0,%1,%2,%3};"
        : "+f"(c[0]), "+f"(c[1]), "+f"(c[2]), "+f"(c[3])
        : "r"(a[0]), "r"(a[1]), "r"(a[2]), "r"(a[3]), "r"(b[0]), "r"(b[1]));
}
__device__ __forceinline__ void split_fp16(float v, __half& hi, __half& lo) {
    hi = __float2half_rn(v);
    lo = __float2half_rn(v - __half2float(hi));
}

// ---------------- SMEM geometry ---------------------------------------------
#define TROW 80
#define TILE_B (128 * TROW)          // 10240 B
#define STAGE_B (4 * TILE_B)         // Ah, Al, Bh, Bl (reduce/xxt)
#define STAGE2_B (2 * TILE_B)        // Ah, Bh         (ygemm/conv)
#define DYN_SMEM (2 * STAGE_B)       // 81920 B
#define DYN2_SMEM (2 * STAGE2_B)     // 40960 B (ygemm)
#define DYNC_SMEM (3 * STAGE2_B)     // 61440 B (conv, 3-stage)

// contiguous 128x32 tile load via cp.async: 512 16B chunks / 256 threads
__device__ __forceinline__ void cpa_tile(uint32_t sdst, const __half* g,
                                         size_t stride, int k0, int tid) {
    #pragma unroll
    for (int it = 0; it < 2; it++) {
        int ch = it * 256 + tid;
        int row = ch >> 2, seg = ch & 3;
        cp16(sdst + row * TROW + seg * 16,
             g + (size_t)row * stride + k0 + seg * 8);
    }
}
__device__ __forceinline__ void cpa_tile_clamp(uint32_t sdst, const __half* g,
                                               size_t stride, int row0,
                                               int maxrow, int k0, int tid) {
    #pragma unroll
    for (int it = 0; it < 2; it++) {
        int ch = it * 256 + tid;
        int row = ch >> 2, seg = ch & 3;
        int rg = row0 + row; if (rg > maxrow) rg = maxrow;
        cp16(sdst + row * TROW + seg * 16,
             g + (size_t)rg * stride + k0 + seg * 8);
    }
}

// one k16 slab: 4 m-atoms x 4 n-atoms of m16n8k16
__device__ __forceinline__ void mma_k16(uint32_t aBase, uint32_t bBase, int kk,
                                        int lane, float c[4][4][4]) {
    uint32_t a[4][4], b[4][2];
    int arow = lane & 15, asel = lane >> 4;
    #pragma unroll
    for (int am = 0; am < 4; am++)
        ldm4(a[am], aBase + (am * 16 + arow) * TROW + (kk + asel * 8) * 2);
    int brow = lane & 7, bsel = (lane >> 3) & 1;
    #pragma unroll
    for (int bn = 0; bn < 4; bn++)
        ldm2(b[bn], bBase + (bn * 8 + brow) * TROW + (kk + bsel * 8) * 2);
    #pragma unroll
    for (int am = 0; am < 4; am++)
        #pragma unroll
        for (int bn = 0; bn < 4; bn++)
            mma16816(c[am][bn], a[am], b[bn]);
}

// full 3-term stage (reduce/xxt): (Ah,Bh), (Ah,Bl), (Al,Bh)
__device__ __forceinline__ void stage_compute(uint32_t sb, int wm, int wn,
                                              int lane, float c[4][4][4]) {
    uint32_t Ah = sb + wm * TROW,              Al = Ah + TILE_B;
    uint32_t Bh = sb + 2 * TILE_B + wn * TROW, Bl = Bh + TILE_B;
    #pragma unroll
    for (int kk = 0; kk < 32; kk += 16) {
        mma_k16(Ah, Bh, kk, lane, c);
        mma_k16(Ah, Bl, kk, lane, c);
        mma_k16(Al, Bh, kk, lane, c);
    }
}
// 1-term stage (ygemm/conv): Ah x Bh
__device__ __forceinline__ void stage_compute_1(uint32_t sb, int wm, int wn,
                                                int lane, float c[4][4][4]) {
    uint32_t Ah = sb + wm * TROW;
    uint32_t Bh = sb + TILE_B + wn * TROW;
    #pragma unroll
    for (int kk = 0; kk < 32; kk += 16) mma_k16(Ah, Bh, kk, lane, c);
}

#define GEMM_VARS()                                                            \
    extern __shared__ __align__(16) char dsm[];                                \
    uint32_t sb0 = smem_u32(dsm);                                              \
    int tid = threadIdx.x, wid = tid >> 5, lane = tid & 31;                    \
    int wm = (wid >> 2) * 64, wn = (wid & 3) * 32;                             \
    float c[4][4][4] = {};

// ---------------- small prep kernels ----------------------------------------
__global__ void k_zero() {
    g_zsum[blockIdx.x * blockDim.x + threadIdx.x] = 0.f;
}
__global__ void prep_bn(const float* __restrict__ rb, const float* __restrict__ rg,
                        const float* __restrict__ rbe, const float* __restrict__ rm,
                        const float* __restrict__ rv,
                        const float* __restrict__ cb, const float* __restrict__ cg,
                        const float* __restrict__ cbe, const float* __restrict__ cm,
                        const float* __restrict__ cv) {
    int i = blockIdx.x * blockDim.x + threadIdx.x;
    if (i < CMID) {
        float inv = rg[i] * rsqrtf(rv[i] + EPS);
        g_scale1[i] = inv;
        g_shift1[i] = (rb[i] - rm[i]) * inv + rbe[i];
        float inv3 = cg[i] * rsqrtf(cv[i] + EPS);
        g_scale3[i] = inv3;
        g_shift3[i] = (cb[i] - cm[i]) * inv3 + cbe[i];
    }
}
__global__ void cvt_w1(const float* __restrict__ w) {
    int i = blockIdx.x * blockDim.x + threadIdx.x;
    __half hi, lo; split_fp16(w[i], hi, lo);
    g_w1_h[i] = hi; g_w1_l[i] = lo;
}
__global__ void cvt_w3(const float* __restrict__ w) {
    int i = blockIdx.x * blockDim.x + threadIdx.x;   // over 512*4608
    int o = i / K33, k = i - o * K33;
    int rs = k >> 9, cc = k & 511;
    int r = rs / 3, s = rs - r * 3;
    g_w3_h[i] = __float2half_rn(w[((o * CMID + cc) * 3 + r) * 3 + s]);
}
// transpose + split features: F[b][c][hw] -> g_fT[b*196+hw][c]
__global__ void cvt_f(const float* __restrict__ f2, const float* __restrict__ f3) {
    __shared__ float t[32][33];
    int hw0 = blockIdx.x * 32, c0 = blockIdx.y * 32, b = blockIdx.z;
    const float* F = (b < HB) ? f2 + (size_t)b * CIN * HW
                              : f3 + (size_t)(b - HB) * CIN * HW;
    int tx = threadIdx.x, ty = threadIdx.y;
    #pragma unroll
    for (int k = 0; k < 4; k++) {
        int cc = c0 + ty + k * 8, hw = hw0 + tx;
        t[ty + k * 8][tx] = (hw < HW) ? F[(size_t)cc * HW + hw] : 0.f;
    }
    __syncthreads();
    #pragma unroll
    for (int k = 0; k < 4; k++) {
        int hw = hw0 + ty + k * 8;
        if (hw < HW) {
            float v = t[tx][ty + k * 8];
            __half hi, lo; split_fp16(v, hi, lo);
            size_t idx = ((size_t)b * HW + hw) * CIN + c0 + tx;
            g_fT_h[idx] = hi; g_fT_l[idx] = lo;
        }
    }
}

// ---------------- K1: reduce GEMM (M=512, N=25088, K=2048) + BN/ReLU --------
// grid (4 m, 196 n): m fastest -> 4 consecutive CTAs share each B tile in L2
__global__ __launch_bounds__(256, 2) void k_reduce_mma() {
    GEMM_VARS();
    int m0 = blockIdx.x * 128, n0 = blockIdx.y * 128;
    const int T = CIN / 32;    // 64 stages
    const __half* Awh = g_w1_h + (size_t)m0 * CIN;
    const __half* Awl = g_w1_l + (size_t)m0 * CIN;
    const __half* Bfh = g_fT_h + (size_t)n0 * CIN;
    const __half* Bfl = g_fT_l + (size_t)n0 * CIN;
    #define ISSUE(kt) {                                                        \
        uint32_t s = sb0 + ((kt) & 1) * STAGE_B; int k0 = (kt) * 32;           \
        cpa_tile(s,              Awh, CIN, k0, tid);                           \
        cpa_tile(s + TILE_B,     Awl, CIN, k0, tid);                           \
        cpa_tile(s + 2 * TILE_B, Bfh, CIN, k0, tid);                           \
        cpa_tile(s + 3 * TILE_B, Bfl, CIN, k0, tid); }
    ISSUE(0); cp_commit();
    for (int kt = 0; kt < T; kt++) {
        if (kt + 1 < T) { ISSUE(kt + 1); cp_commit(); cp_wait<1>(); }
        else cp_wait<0>();
        __syncthreads();
        stage_compute(sb0 + (kt & 1) * STAGE_B, wm, wn, lane, c);
        __syncthreads();
    }
    #undef ISSUE
    #pragma unroll
    for (int am = 0; am < 4; am++) {
        #pragma unroll
        for (int half = 0; half < 2; half++) {
            int o = m0 + wm + am * 16 + (lane >> 2) + half * 8;
            float sc = g_scale1[o], sh = g_shift1[o];
            #pragma unroll
            for (int bn = 0; bn < 4; bn++) {
                #pragma unroll
                for (int e = 0; e < 2; e++) {
                    float v = c[am][bn][half * 2 + e];
                    v = fmaxf(v * sc + sh, 0.f);
                    int col = n0 + wn + bn * 8 + 2 * (lane & 3) + e;
                    int b = col / HW, hw = col - b * HW;
                    __half hi, lo; split_fp16(v, hi, lo);
                    size_t i1 = ((size_t)b * CMID + o) * HWP + hw;
                    g_x_h[i1] = hi; g_x_l[i1] = lo;
                    g_xT_h[((size_t)b * HW + hw) * CMID + o] = hi;
                }
            }
        }
    }
}

// ---------------- K2: XXt per batch (M=N=512, K=196 pad 224) ----------------
__global__ __launch_bounds__(256, 2) void k_xxt_mma() {
    GEMM_VARS();
    int n0 = blockIdx.x * 128, m0 = blockIdx.y * 128, b = blockIdx.z;
    const __half* Xh = g_x_h + (size_t)b * CMID * HWP;
    const __half* Xl = g_x_l + (size_t)b * CMID * HWP;
    const int T = KXT / 32;    // 7 stages
    #define ISSUE(kt) {                                                        \
        uint32_t s = sb0 + ((kt) & 1) * STAGE_B; int k0 = (kt) * 32;           \
        cpa_tile(s,              Xh + (size_t)m0 * HWP, HWP, k0, tid);         \
        cpa_tile(s + TILE_B,     Xl + (size_t)m0 * HWP, HWP, k0, tid);         \
        cpa_tile(s + 2 * TILE_B, Xh + (size_t)n0 * HWP, HWP, k0, tid);         \
        cpa_tile(s + 3 * TILE_B, Xl + (size_t)n0 * HWP, HWP, k0, tid); }
    ISSUE(0); cp_commit();
    for (int kt = 0; kt < T; kt++) {
        if (kt + 1 < T) { ISSUE(kt + 1); cp_commit(); cp_wait<1>(); }
        else cp_wait<0>();
        __syncthreads();
        stage_compute(sb0 + (kt & 1) * STAGE_B, wm, wn, lane, c);
        __syncthreads();
    }
    #undef ISSUE
    float* out = g_att + (size_t)b * CMID * CMID;
    #pragma unroll
    for (int am = 0; am < 4; am++)
        #pragma unroll
        for (int half = 0; half < 2; half++) {
            int r = m0 + wm + am * 16 + (lane >> 2) + half * 8;
            #pragma unroll
            for (int bn = 0; bn < 4; bn++) {
                int col = n0 + wn + bn * 8 + 2 * (lane & 3);
                out[(size_t)r * CMID + col]     = c[am][bn][half * 2 + 0];
                out[(size_t)r * CMID + col + 1] = c[am][bn][half * 2 + 1];
            }
        }
}

// ---------------- K3: softmax(-S) rowwise -> fp16 (single) ------------------
__global__ __launch_bounds__(256) void k_softmax() {
    int gw = (blockIdx.x * blockDim.x + threadIdx.x) >> 5;
    int lane = threadIdx.x & 31;
    if (gw >= BATCH * CMID) return;
    const float* row = g_att + (size_t)gw * CMID;
    float mn = CUDART_INF_F;
    #pragma unroll
    for (int t = 0; t < 16; t++) mn = fminf(mn, row[lane + t * 32]);
    #pragma unroll
    for (int o = 16; o; o >>= 1) mn = fminf(mn, __shfl_xor_sync(~0u, mn, o));
    float e[16], sum = 0.f;
    #pragma unroll
    for (int t = 0; t < 16; t++) { e[t] = __expf(mn - row[lane + t * 32]); sum += e[t]; }
    #pragma unroll
    for (int o = 16; o; o >>= 1) sum += __shfl_xor_sync(~0u, sum, o);
    float inv = 1.f / sum;
    #pragma unroll
    for (int t = 0; t < 16; t++)
        g_att_h[(size_t)gw * CMID + lane + t * 32] = __float2half_rn(e[t] * inv);
}

// ---------------- K4: y = att @ X (M=512, N=196pad256, K=512), 1-term -------
__global__ __launch_bounds__(256, 2) void k_ygemm_mma() {
    GEMM_VARS();
    int n0 = blockIdx.x * 128, m0 = blockIdx.y * 128, b = blockIdx.z;
    const __half* Ah = g_att_h + ((size_t)b * CMID + m0) * CMID;
    const __half* Bh = g_xT_h + (size_t)b * HW * CMID;
    const int T = CMID / 32;   // 16 stages
    #define ISSUE(kt) {                                                        \
        uint32_t s = sb0 + ((kt) & 1) * STAGE2_B; int k0 = (kt) * 32;          \
        cpa_tile(s, Ah, CMID, k0, tid);                                        \
        cpa_tile_clamp(s + TILE_B, Bh, CMID, n0, HW - 1, k0, tid); }
    ISSUE(0); cp_commit();
    for (int kt = 0; kt < T; kt++) {
        if (kt + 1 < T) { ISSUE(kt + 1); cp_commit(); cp_wait<1>(); }
        else cp_wait<0>();
        __syncthreads();
        stage_compute_1(sb0 + (kt & 1) * STAGE2_B, wm, wn, lane, c);
        __syncthreads();
    }
    #undef ISSUE
    #pragma unroll
    for (int am = 0; am < 4; am++)
        #pragma unroll
        for (int half = 0; half < 2; half++) {
            int i = m0 + wm + am * 16 + (lane >> 2) + half * 8;
            #pragma unroll
            for (int bn = 0; bn < 4; bn++)
                #pragma unroll
                for (int e = 0; e < 2; e++) {
                    int col = n0 + wn + bn * 8 + 2 * (lane & 3) + e;
                    if (col < HW)
                        g_yT_h[((size_t)b * HW + col) * CMID + i] =
                            __float2half_rn(c[am][bn][half * 2 + e]);
                }
        }
}

// ---------------- K5: conv3 implicit GEMM (M=512, N=25088, K=4608), 1-term --
// grid (4 m, 196 n). 3-stage pipeline. K reordered (rs, c).
__global__ __launch_bounds__(256, 2) void k_conv_mma() {
    GEMM_VARS();
    int m0 = blockIdx.x * 128, n0 = blockIdx.y * 128;
    const int T = K33 / 32;    // 144 stages
    int gr[2], gb[2], gph[2], gpw[2];
    #pragma unroll
    for (int it = 0; it < 2; it++) {
        int row = it * 64 + (tid >> 2);
        gr[it] = row;
        int col = n0 + row;
        gb[it] = col / HW;
        int p = col - gb[it] * HW;
        gph[it] = p / 14; gpw[it] = p - gph[it] * 14;
    }
    int seg = tid & 3;
    #define ISSUE(kt) {                                                        \
        uint32_t s = sb0 + ((kt) % 3) * STAGE2_B; int k0 = (kt) * 32;          \
        cpa_tile(s, g_w3_h + (size_t)m0 * K33, K33, k0, tid);                  \
        int rs = (kt) >> 4, c0 = ((kt) & 15) * 32;                             \
        int dr = rs / 3 - 1, ds = rs - (rs / 3) * 3 - 1;                       \
        _Pragma("unroll")                                                      \
        for (int it = 0; it < 2; it++) {                                       \
            int ih = gph[it] + dr, iw = gpw[it] + ds;                          \
            int ok = ((unsigned)ih < 14u) && ((unsigned)iw < 14u);             \
            size_t pix = (size_t)gb[it] * HW + (ok ? ih * 14 + iw : 0);        \
            size_t gidx = pix * CMID + c0 + seg * 8;                           \
            cp16z(s + TILE_B + gr[it] * TROW + seg * 16, g_yT_h + gidx, ok);   \
        } }
    ISSUE(0); cp_commit();
    ISSUE(1); cp_commit();
    for (int kt = 0; kt < T; kt++) {
        if (kt + 2 < T) { ISSUE(kt + 2); cp_commit(); cp_wait<2>(); }
        else if (kt + 1 < T) cp_wait<1>();
        else cp_wait<0>();
        __syncthreads();
        stage_compute_1(sb0 + (kt % 3) * STAGE2_B, wm, wn, lane, c);
        __syncthreads();
    }
    #undef ISSUE
    // fused BN + ReLU + GAP
    int b0 = n0 / HW;
    int split = (b0 + 1) * HW - n0;   // local cols < split belong to b0
    #pragma unroll
    for (int am = 0; am < 4; am++)
        #pragma unroll
        for (int half = 0; half < 2; half++) {
            int o = m0 + wm + am * 16 + (lane >> 2) + half * 8;
            float sc = g_scale3[o], sh = g_shift3[o];
            float s0 = 0.f, s1 = 0.f;
            #pragma unroll
            for (int bn = 0; bn < 4; bn++)
                #pragma unroll
                for (int e = 0; e < 2; e++) {
                    float v = fmaxf(c[am][bn][half * 2 + e] * sc + sh, 0.f);
                    int lcol = wn + bn * 8 + 2 * (lane & 3) + e;
                    if (lcol < split) s0 += v; else s1 += v;
                }
            s0 += __shfl_xor_sync(~0u, s0, 1);
            s0 += __shfl_xor_sync(~0u, s0, 2);
            s1 += __shfl_xor_sync(~0u, s1, 1);
            s1 += __shfl_xor_sync(~0u, s1, 2);
            if ((lane & 3) == 0) {
                atomicAdd(&g_zsum[b0 * CMID + o], s0 * (1.f / HW));
                if (split < 128)
                    atomicAdd(&g_zsum[(b0 + 1) * CMID + o], s1 * (1.f / HW));
            }
        }
}

// ---------------- K7: fc1 + ReLU --------------------------------------------
__global__ __launch_bounds__(256) void k_fc1(const float* __restrict__ w,
                                             const float* __restrict__ bias) {
    int gw = (blockIdx.x * blockDim.x + threadIdx.x) >> 5;
    int lane = threadIdx.x & 31;
    if (gw >= BATCH * 200) return;
    int b = gw / 200, j = gw - b * 200;
    const float* zr = g_zsum + b * CMID;
    const float* wr = w + (size_t)j * CMID;
    float s = 0.f;
    for (int k = lane; k < CMID; k += 32) s += zr[k] * wr[k];
    #pragma unroll
    for (int o = 16; o; o >>= 1) s += __shfl_xor_sync(~0u, s, o);
    if (lane == 0) g_h[gw] = fmaxf(s + bias[j], 0.f);
}

// ---------------- K8: fc2 + branch-sum --------------------------------------
__global__ __launch_bounds__(256) void k_fc2(const float* __restrict__ w,
                                             const float* __restrict__ bias,
                                             float* __restrict__ out) {
    int gw = (blockIdx.x * blockDim.x + threadIdx.x) >> 5;
    int lane = threadIdx.x & 31;
    if (gw >= HB * 200) return;
    int b = gw / 200, j = gw - b * 200;
    const float* h1 = g_h + (size_t)b * 200;
    const float* h2 = g_h + (size_t)(b + HB) * 200;
    const float* wr = w + (size_t)j * 200;
    float s = 0.f;
    for (int k = lane; k < 200; k += 32) s += (h1[k] + h2[k]) * wr[k];
    #pragma unroll
    for (int o = 16; o; o >>= 1) s += __shfl_xor_sync(~0u, s, o);
    if (lane == 0) out[gw] = s + 2.f * bias[j];
}

// ---------------- launch ----------------------------------------------------
extern "C" void kernel_launch(void* const* d_in, const int* in_sizes, int n_in,
                              void* d_out, int out_size) {
    const float* f2  = (const float*)d_in[0];
    const float* f3  = (const float*)d_in[1];
    const float* rw  = (const float*)d_in[2];
    const float* rb  = (const float*)d_in[3];
    const float* rg  = (const float*)d_in[4];
    const float* rbe = (const float*)d_in[5];
    const float* rm  = (const float*)d_in[6];
    const float* rv  = (const float*)d_in[7];
    const float* c3w = (const float*)d_in[8];
    const float* c3b = (const float*)d_in[9];
    const float* c3g = (const float*)d_in[10];
    const float* c3be= (const float*)d_in[11];
    const float* c3m = (const float*)d_in[12];
    const float* c3v = (const float*)d_in[13];
    const float* f1w = (const float*)d_in[14];
    const float* f1b = (const float*)d_in[15];
    const float* f2w = (const float*)d_in[16];
    const float* f2b = (const float*)d_in[17];
    float* out = (float*)d_out;

    cudaFuncSetAttribute(k_reduce_mma, cudaFuncAttributeMaxDynamicSharedMemorySize, DYN_SMEM);
    cudaFuncSetAttribute(k_xxt_mma,    cudaFuncAttributeMaxDynamicSharedMemorySize, DYN_SMEM);
    cudaFuncSetAttribute(k_ygemm_mma,  cudaFuncAttributeMaxDynamicSharedMemorySize, DYN2_SMEM);
    cudaFuncSetAttribute(k_conv_mma,   cudaFuncAttributeMaxDynamicSharedMemorySize, DYNC_SMEM);

    k_zero<<<BATCH * CMID / 256, 256>>>();
    prep_bn<<<2, 256>>>(rb, rg, rbe, rm, rv, c3b, c3g, c3be, c3m, c3v);
    cvt_w1<<<(CMID * CIN) / 256, 256>>>(rw);
    cvt_w3<<<(CMID * K33) / 256, 256>>>(c3w);
    cvt_f<<<dim3(7, CIN / 32, BATCH), dim3(32, 8)>>>(f2, f3);

    k_reduce_mma<<<dim3(4, NFLAT / 128), 256, DYN_SMEM>>>();
    k_xxt_mma<<<dim3(4, 4, BATCH), 256, DYN_SMEM>>>();
    k_softmax<<<(BATCH * CMID) / 8, 256>>>();
    k_ygemm_mma<<<dim3(2, 4, BATCH), 256, DYN2_SMEM>>>();
    k_conv_mma<<<dim3(4, NFLAT / 128), 256, DYNC_SMEM>>>();
    k_fc1<<<(BATCH * 200 + 7) / 8, 256>>>(f1w, f1b);
    k_fc2<<<(HB * 200 + 7) / 8, 256>>>(f2w, f2b, out);
}